// round 7
// baseline (speedup 1.0000x reference)
#include <cuda_runtime.h>
#include <cuda_bf16.h>
#include <math.h>
#include <stdint.h>

#define Bb   8
#define Cc   256
#define Hh   64
#define Ww   64
#define Oo   256
#define HW   4096
#define OCOFF 27
#define KTOT 2304            /* K = C*9 */
#define NTOT 32768           /* B*H*W */
#define CSPLIT 8
#define CPG (Cc / CSPLIT)

// ---------------- scratch (__device__ globals) ------------------------------
__device__ float    g_part[CSPLIT][Bb * OCOFF * HW];   // offset-conv partials
__device__ uint16_t g_AH[Oo * KTOT];                   // weight hi, [o][k]
__device__ uint16_t g_AL[Oo * KTOT];                   // weight lo, [o][k]

// ---------------- helpers ----------------------------------------------------
__device__ __forceinline__ uint32_t smem_u32(const void* p) {
    uint32_t a;
    asm("{ .reg .u64 t; cvta.to.shared.u64 t, %1; cvt.u32.u64 %0, t; }" : "=r"(a) : "l"(p));
    return a;
}
__device__ __forceinline__ uint32_t swz(uint32_t off)  { return off ^ ((off >> 3) & 0x70); }
__device__ __forceinline__ uint32_t swz2(uint32_t off) { return off ^ ((off >> 4) & 0x70); }

__device__ __forceinline__ void cp16(uint32_t dst, const void* src) {
    asm volatile("cp.async.cg.shared.global [%0], [%1], 16;" :: "r"(dst), "l"(src));
}
#define CP_COMMIT() asm volatile("cp.async.commit_group;" ::: "memory")
#define CP_WAIT1()  asm volatile("cp.async.wait_group 1;" ::: "memory")

__device__ __forceinline__ void ldsm4(uint32_t* r, uint32_t addr) {
    asm volatile("ldmatrix.sync.aligned.m8n8.x4.shared.b16 {%0,%1,%2,%3}, [%4];"
                 : "=r"(r[0]), "=r"(r[1]), "=r"(r[2]), "=r"(r[3]) : "r"(addr));
}
__device__ __forceinline__ void ldsm4t(uint32_t* r, uint32_t addr) {
    asm volatile("ldmatrix.sync.aligned.m8n8.x4.trans.shared.b16 {%0,%1,%2,%3}, [%4];"
                 : "=r"(r[0]), "=r"(r[1]), "=r"(r[2]), "=r"(r[3]) : "r"(addr));
}
__device__ __forceinline__ void mma16816(float* c, const uint32_t* a,
                                         uint32_t b0, uint32_t b1) {
    asm volatile("mma.sync.aligned.m16n8k16.row.col.f32.bf16.bf16.f32 "
                 "{%0,%1,%2,%3}, {%4,%5,%6,%7}, {%8,%9}, {%0,%1,%2,%3};"
                 : "+f"(c[0]), "+f"(c[1]), "+f"(c[2]), "+f"(c[3])
                 : "r"(a[0]), "r"(a[1]), "r"(a[2]), "r"(a[3]), "r"(b0), "r"(b1));
}
__device__ __forceinline__ void fma2(unsigned long long& a, unsigned long long x,
                                     unsigned long long w) {
    asm("fma.rn.f32x2 %0, %1, %2, %0;" : "+l"(a) : "l"(x), "l"(w));
}
__device__ __forceinline__ unsigned long long pack2(float v) {
    unsigned long long r;
    asm("mov.b64 %0, {%1, %1};" : "=l"(r) : "r"(__float_as_uint(v)));
    return r;
}

// ===========================================================================
// Kernel A: offset conv partials (32-ch groups), packed f32x2 math
// ===========================================================================
__global__ __launch_bounds__(128)
void offset_conv_part(const float* __restrict__ x,
                      const float* __restrict__ w_off) {
    __shared__ float sx[4][64];
    __shared__ __align__(16) float sw2[9 * 28];

    int cg = blockIdx.x & 7;
    int hs = (blockIdx.x >> 3) & 31;
    int b  = blockIdx.x >> 8;
    int h0 = hs << 1;
    int ty = threadIdx.x >> 6;
    int w  = threadIdx.x & 63;
    int h  = h0 + ty;

    if (threadIdx.x < 9) sw2[threadIdx.x * 28 + 27] = 0.f;

    unsigned long long acc2[14];
#pragma unroll
    for (int j = 0; j < 14; ++j) acc2[j] = 0ULL;

    const float* xb = x + (size_t)b * Cc * HW;
    int c0 = cg * CPG;

    for (int ci = 0; ci < CPG; ++ci) {
        int c = c0 + ci;
#pragma unroll
        for (int r = ty; r < 4; r += 2) {
            int yy = h0 - 1 + r;
            sx[r][w] = (yy >= 0 && yy < Hh) ? xb[(size_t)c * HW + yy * 64 + w] : 0.f;
        }
        for (int i = threadIdx.x; i < 243; i += 128) {
            int oc = i / 9, t = i - oc * 9;
            sw2[t * 28 + oc] = w_off[(size_t)oc * KTOT + c * 9 + t];
        }
        __syncthreads();

        float xv[9];
#pragma unroll
        for (int dy = 0; dy < 3; ++dy)
#pragma unroll
            for (int dx = 0; dx < 3; ++dx) {
                int xx = w - 1 + dx;
                xv[dy * 3 + dx] = (xx >= 0 && xx < Ww) ? sx[ty + dy][xx] : 0.f;
            }

#pragma unroll
        for (int t = 0; t < 9; ++t) {
            unsigned long long xp = pack2(xv[t]);
            const ulonglong2* wp = (const ulonglong2*)&sw2[t * 28];
#pragma unroll
            for (int j = 0; j < 7; ++j) {
                ulonglong2 w2 = wp[j];
                fma2(acc2[2 * j],     xp, w2.x);
                fma2(acc2[2 * j + 1], xp, w2.y);
            }
        }
        __syncthreads();
    }

    size_t outb = ((size_t)b * OCOFF) * HW + h * 64 + w;
#pragma unroll
    for (int j = 0; j < 14; ++j) {
        float lo = __uint_as_float((uint32_t)acc2[j]);
        float hi = __uint_as_float((uint32_t)(acc2[j] >> 32));
        int oc0 = 2 * j, oc1 = 2 * j + 1;
        g_part[cg][outb + (size_t)oc0 * HW] = lo;
        if (oc1 < OCOFF) g_part[cg][outb + (size_t)oc1 * HW] = hi;
    }
}

// ===========================================================================
// Kernel W: split weights into bf16 hi (truncate) / lo (residual) planes
// ===========================================================================
__global__ void wprep_kernel(const float* __restrict__ weight) {
    int idx = blockIdx.x * 256 + threadIdx.x;
    if (idx >= Oo * KTOT) return;
    float wv = weight[idx];
    uint32_t vb = __float_as_uint(wv);
    uint32_t hb = vb & 0xFFFF0000u;
    float resid = wv - __uint_as_float(hb);
    g_AH[idx] = (uint16_t)(hb >> 16);
    g_AL[idx] = __bfloat16_as_ushort(__float2bfloat16_rn(resid));
}

// ===========================================================================
// Kernel C: FUSED deform-sample + HMMA 3-term bf16 GEMM.
// M=256 (whole O) x N=128 tiles. Each block produces its own B tile in smem
// (no cols round-trip through DRAM) and reduces offset-conv partials inline.
// out = AH*BH + AL*BH + AH*BL
//
// smem layout:
//   [0, 18432)        wgt  float4[1152]   (kk*128 + n_l)  mask-premult weights
//   [18432, 27648)    offp uint64[1152]   packed clamped offsets (4 x u16)
//   [27648, +98304)   stage0: AH(32768) AL(32768) BH(16384) BL(16384)
//   [125952, +98304)  stage1
// total 224256 B
// ===========================================================================
#define PAR_W   0
#define PAR_O   18432
#define STG0    27648
#define STAGEB  98304
#define A_L_OFF 32768
#define B_H_OFF 65536
#define B_L_OFF 81920
#define GSM     224256
#define NCHUNK  36

__device__ __forceinline__ void loadA(uint32_t sbu, uint32_t stoff, int chunk, int tid) {
    int kw = chunk * 64;
    int r = tid >> 3, q = tid & 7;            // r 0..63
    uint32_t base = sbu + stoff;
#pragma unroll
    for (int rr = 0; rr < 4; ++rr) {
        int row = r + rr * 64;
        uint32_t o = swz((uint32_t)(row * 128 + q * 16));
        cp16(base + o,           &g_AH[(size_t)row * KTOT + kw + q * 8]);
        cp16(base + A_L_OFF + o, &g_AL[(size_t)row * KTOT + kw + q * 8]);
    }
}

__device__ __forceinline__ void produceB(char* smc, uint32_t stoff, int chunk,
                                         const float* __restrict__ xb,
                                         int np, int ks) {
    const float4* wgt = (const float4*)(smc + PAR_W);
    const unsigned long long* offp = (const unsigned long long*)(smc + PAR_O);
    char* bh = smc + stoff + B_H_OFF;
    char* bl = smc + stoff + B_L_OFF;

    int kg = chunk * 64 + ks * 8;
    int c  = kg / 9;
    int kk = kg - c * 9;

#pragma unroll
    for (int j = 0; j < 8; ++j) {
        int pidx = kk * 128 + 2 * np;
        float4 w0 = wgt[pidx];
        float4 w1 = wgt[pidx + 1];
        unsigned long long q0 = offp[pidx];
        unsigned long long q1 = offp[pidx + 1];
        const float* xc = xb + (size_t)c * HW;

        float v0 = xc[(int)(q0 & 4095u)]          * w0.x
                 + xc[(int)((q0 >> 16) & 4095u)]  * w0.y
                 + xc[(int)((q0 >> 32) & 4095u)]  * w0.z
                 + xc[(int)((q0 >> 48) & 4095u)]  * w0.w;
        float v1 = xc[(int)(q1 & 4095u)]          * w1.x
                 + xc[(int)((q1 >> 16) & 4095u)]  * w1.y
                 + xc[(int)((q1 >> 32) & 4095u)]  * w1.z
                 + xc[(int)((q1 >> 48) & 4095u)]  * w1.w;

        uint32_t h0 = __float_as_uint(v0) & 0xFFFF0000u;
        float    r0 = v0 - __uint_as_float(h0);
        uint32_t l0 = __bfloat16_as_ushort(__float2bfloat16_rn(r0));
        uint32_t h1 = __float_as_uint(v1) & 0xFFFF0000u;
        float    r1 = v1 - __uint_as_float(h1);
        uint32_t l1 = __bfloat16_as_ushort(__float2bfloat16_rn(r1));

        int kl = ks * 8 + j;
        uint32_t o = swz2((uint32_t)(kl * 256 + np * 4));
        *(uint32_t*)(bh + o) = (h0 >> 16) | h1;
        *(uint32_t*)(bl + o) = l0 | (l1 << 16);

        if (++kk == 9) { kk = 0; ++c; }
    }
}

__global__ __launch_bounds__(512, 1)
void gemm_fused_kernel(const float* __restrict__ x,
                       const float* __restrict__ b_off,
                       const float* __restrict__ bias,
                       const float* __restrict__ gamma,
                       const float* __restrict__ beta,
                       const float* __restrict__ rmean,
                       const float* __restrict__ rvar,
                       float* __restrict__ out) {
    extern __shared__ char smc[];
    uint32_t sbu = smem_u32(smc);
    int tid  = threadIdx.x;
    int lane = tid & 31;
    int wid  = tid >> 5;
    int bn = blockIdx.x * 128;
    int bimg = bn >> 12;                       // whole block within one image
    const float* xb = x + (size_t)bimg * Cc * HW;

    // ---------------- params phase: fused offset reduce + sampling setup ----
    {
        float4* wgt = (float4*)(smc + PAR_W);
        unsigned long long* offp = (unsigned long long*)(smc + PAR_O);
        for (int idx = tid; idx < 1152; idx += 512) {
            int kk  = idx >> 7;
            int n_l = idx & 127;
            int hw  = (bn + n_l) & 4095;
            int h = hw >> 6, w = hw & 63;
            size_t base = ((size_t)bimg * OCOFF) * HW + hw;
            float oy = 0.f, ox = 0.f, ms = 0.f;
#pragma unroll
            for (int g = 0; g < CSPLIT; ++g) {
                oy += g_part[g][base + (size_t)kk * HW];
                ox += g_part[g][base + (size_t)(9 + kk) * HW];
                ms += g_part[g][base + (size_t)(18 + kk) * HW];
            }
            oy += b_off[kk]; ox += b_off[9 + kk]; ms += b_off[18 + kk];
            float m = 1.f / (1.f + expf(-ms));

            float py = (float)(h - 1 + kk / 3) + oy;
            float px = (float)(w - 1 + kk % 3) + ox;
            float y0f = floorf(py), x0f = floorf(px);
            float wy = py - y0f, wx = px - x0f;
            int y0 = (int)y0f, x0 = (int)x0f;

            bool yv0 = (y0 >= 0) & (y0 < Hh);
            bool yv1 = (y0 + 1 >= 0) & (y0 + 1 < Hh);
            bool xv0 = (x0 >= 0) & (x0 < Ww);
            bool xv1 = (x0 + 1 >= 0) & (x0 + 1 < Ww);

            float4 wv;
            wv.x = m * (1.f - wy) * (1.f - wx) * (float)(yv0 & xv0);
            wv.y = m * (1.f - wy) * wx         * (float)(yv0 & xv1);
            wv.z = m * wy * (1.f - wx)         * (float)(yv1 & xv0);
            wv.w = m * wy * wx                 * (float)(yv1 & xv1);

            int y0c = min(max(y0, 0), Hh - 1);
            int y1c = min(max(y0 + 1, 0), Hh - 1);
            int x0c = min(max(x0, 0), Ww - 1);
            int x1c = min(max(x0 + 1, 0), Ww - 1);
            unsigned long long o00 = (unsigned long long)(y0c * 64 + x0c);
            unsigned long long o01 = (unsigned long long)(y0c * 64 + x1c);
            unsigned long long o10 = (unsigned long long)(y1c * 64 + x0c);
            unsigned long long o11 = (unsigned long long)(y1c * 64 + x1c);

            wgt[idx]  = wv;
            offp[idx] = o00 | (o01 << 16) | (o10 << 32) | (o11 << 48);
        }
    }
    __syncthreads();

    // ---------------- pipeline prologue ----------
    int np = tid & 63;           // n-pair index (covers n_l = 2np, 2np+1)
    int ks = tid >> 6;           // 0..7, covers k_l = ks*8 .. ks*8+7

    loadA(sbu, STG0, 0, tid);           CP_COMMIT();
    loadA(sbu, STG0 + STAGEB, 1, tid);  CP_COMMIT();
    produceB(smc, STG0, 0, xb, np, ks);

    // lane pieces
    int warp_m = wid & 7;
    int warp_n = wid >> 3;
    int mi   = lane >> 3;
    int mrow = lane & 7;
    int rbit = ((mi & 1) << 3) + mrow;
    int cbit = (mi >> 1) << 4;
    int klane = ((mi >> 1) << 3) + mrow;
    int nlane = (mi & 1) << 3;
    int arow0 = warp_m * 32;
    int brow0 = warp_n * 64;

    float acc[2][8][4];
#pragma unroll
    for (int a = 0; a < 2; ++a)
#pragma unroll
        for (int b2 = 0; b2 < 8; ++b2)
#pragma unroll
            for (int c2 = 0; c2 < 4; ++c2) acc[a][b2][c2] = 0.f;

    // ---------------- main loop ----------
    for (int i = 0; i < NCHUNK; ++i) {
        int st = i & 1;
        uint32_t stoff = STG0 + st * STAGEB;
        CP_WAIT1();
        __syncthreads();

        // producer first: LDG latency hides under the MMA stream below
        if (i + 1 < NCHUNK)
            produceB(smc, STG0 + (st ^ 1) * STAGEB, i + 1, xb, np, ks);

        uint32_t base = sbu + stoff;
#pragma unroll
        for (int kss = 0; kss < 4; ++kss) {
            int kb = kss * 32;
            uint32_t boffs[4], aoffs[2];
#pragma unroll
            for (int ng = 0; ng < 4; ++ng)
                boffs[ng] = swz2((uint32_t)((kss * 16 + klane) * 256
                                 + (brow0 + ng * 16 + nlane) * 2));
#pragma unroll
            for (int mt = 0; mt < 2; ++mt)
                aoffs[mt] = swz((uint32_t)((arow0 + mt * 16 + rbit) * 128 + kb + cbit));

            uint32_t bq[4][4], ah[2][4];
#pragma unroll
            for (int ng = 0; ng < 4; ++ng) ldsm4t(bq[ng], base + B_H_OFF + boffs[ng]);
#pragma unroll
            for (int mt = 0; mt < 2; ++mt) ldsm4(ah[mt], base + aoffs[mt]);

            // AH x BH
#pragma unroll
            for (int mt = 0; mt < 2; ++mt)
#pragma unroll
                for (int ng = 0; ng < 4; ++ng) {
                    mma16816(acc[mt][ng * 2 + 0], ah[mt], bq[ng][0], bq[ng][2]);
                    mma16816(acc[mt][ng * 2 + 1], ah[mt], bq[ng][1], bq[ng][3]);
                }
            // AL x BH
#pragma unroll
            for (int mt = 0; mt < 2; ++mt) {
                uint32_t al[4];
                ldsm4(al, base + A_L_OFF + aoffs[mt]);
#pragma unroll
                for (int ng = 0; ng < 4; ++ng) {
                    mma16816(acc[mt][ng * 2 + 0], al, bq[ng][0], bq[ng][2]);
                    mma16816(acc[mt][ng * 2 + 1], al, bq[ng][1], bq[ng][3]);
                }
            }
            // AH x BL
#pragma unroll
            for (int ng = 0; ng < 4; ++ng) ldsm4t(bq[ng], base + B_L_OFF + boffs[ng]);
#pragma unroll
            for (int mt = 0; mt < 2; ++mt)
#pragma unroll
                for (int ng = 0; ng < 4; ++ng) {
                    mma16816(acc[mt][ng * 2 + 0], ah[mt], bq[ng][0], bq[ng][2]);
                    mma16816(acc[mt][ng * 2 + 1], ah[mt], bq[ng][1], bq[ng][3]);
                }
        }
        __syncthreads();
        if (i + 2 < NCHUNK) loadA(sbu, stoff, i + 2, tid);
        CP_COMMIT();
    }

    // ---------------- epilogue: BN + bias + ReLU, float2 stores ----------
    int nbase = bn + warp_n * 64;
#pragma unroll
    for (int mt = 0; mt < 2; ++mt) {
        int o0 = warp_m * 32 + mt * 16 + (lane >> 2);
        int o1 = o0 + 8;
        float inv0 = gamma[o0] * rsqrtf(rvar[o0] + 1e-5f);
        float sh0  = beta[o0] - rmean[o0] * inv0 + bias[o0] * inv0;
        float inv1 = gamma[o1] * rsqrtf(rvar[o1] + 1e-5f);
        float sh1  = beta[o1] - rmean[o1] * inv1 + bias[o1] * inv1;
#pragma unroll
        for (int nt = 0; nt < 8; ++nt) {
            int n = nbase + nt * 8 + ((lane & 3) << 1);
            int bi = n >> 12;
            int hw = n & 4095;
            float2 v0, v1;
            v0.x = fmaxf(fmaf(acc[mt][nt][0], inv0, sh0), 0.f);
            v0.y = fmaxf(fmaf(acc[mt][nt][1], inv0, sh0), 0.f);
            v1.x = fmaxf(fmaf(acc[mt][nt][2], inv1, sh1), 0.f);
            v1.y = fmaxf(fmaf(acc[mt][nt][3], inv1, sh1), 0.f);
            *(float2*)&out[(((size_t)(bi * Oo + o0)) << 12) + hw] = v0;
            *(float2*)&out[(((size_t)(bi * Oo + o1)) << 12) + hw] = v1;
        }
    }
}

// ===========================================================================
extern "C" void kernel_launch(void* const* d_in, const int* in_sizes, int n_in,
                              void* d_out, int out_size) {
    const float* x      = (const float*)d_in[0];
    const float* w_off  = (const float*)d_in[1];
    const float* b_off  = (const float*)d_in[2];
    const float* weight = (const float*)d_in[3];
    const float* bias   = (const float*)d_in[4];
    const float* gamma  = (const float*)d_in[5];
    const float* beta   = (const float*)d_in[6];
    const float* rmean  = (const float*)d_in[7];
    const float* rvar   = (const float*)d_in[8];
    float* out = (float*)d_out;

    cudaFuncSetAttribute(gemm_fused_kernel,
                         cudaFuncAttributeMaxDynamicSharedMemorySize, GSM);

    wprep_kernel<<<(Oo * KTOT + 255) / 256, 256>>>(weight);
    offset_conv_part<<<Bb * 32 * CSPLIT, 128>>>(x, w_off);

    gemm_fused_kernel<<<NTOT / 128, 512, GSM>>>(x, b_off, bias, gamma, beta,
                                                rmean, rvar, out);
}

// round 8
// speedup vs baseline: 1.3557x; 1.3557x over previous
#include <cuda_runtime.h>
#include <cuda_fp16.h>
#include <math.h>
#include <stdint.h>

#define Bb   8
#define Cc   256
#define Hh   64
#define Ww   64
#define Oo   256
#define HW   4096
#define OCOFF 27
#define KTOT 2304            /* K = C*9 */
#define NTOT 32768           /* B*H*W */
#define CSPLIT 8
#define CPG (Cc / CSPLIT)

// ---------------- scratch (__device__ globals) ------------------------------
__device__ float    g_part[CSPLIT][Bb * OCOFF * HW];   // offset-conv partials
__device__ uint16_t g_cols[(size_t)KTOT * NTOT];       // fp16 cols, [k][n]
__device__ uint16_t g_AH[Oo * KTOT];                   // weight fp16 hi, [o][k]
__device__ uint16_t g_AL[Oo * KTOT];                   // weight fp16 residual

// ---------------- helpers ----------------------------------------------------
__device__ __forceinline__ uint32_t smem_u32(const void* p) {
    uint32_t a;
    asm("{ .reg .u64 t; cvta.to.shared.u64 t, %1; cvt.u32.u64 %0, t; }" : "=r"(a) : "l"(p));
    return a;
}
__device__ __forceinline__ uint32_t swz(uint32_t off)  { return off ^ ((off >> 3) & 0x70); }
__device__ __forceinline__ uint32_t swz2(uint32_t off) { return off ^ ((off >> 4) & 0x70); }

__device__ __forceinline__ void cp16(uint32_t dst, const void* src) {
    asm volatile("cp.async.cg.shared.global [%0], [%1], 16;" :: "r"(dst), "l"(src));
}
#define CP_COMMIT() asm volatile("cp.async.commit_group;" ::: "memory")
#define CP_WAIT1()  asm volatile("cp.async.wait_group 1;" ::: "memory")

__device__ __forceinline__ void ldsm4(uint32_t* r, uint32_t addr) {
    asm volatile("ldmatrix.sync.aligned.m8n8.x4.shared.b16 {%0,%1,%2,%3}, [%4];"
                 : "=r"(r[0]), "=r"(r[1]), "=r"(r[2]), "=r"(r[3]) : "r"(addr));
}
__device__ __forceinline__ void ldsm4t(uint32_t* r, uint32_t addr) {
    asm volatile("ldmatrix.sync.aligned.m8n8.x4.trans.shared.b16 {%0,%1,%2,%3}, [%4];"
                 : "=r"(r[0]), "=r"(r[1]), "=r"(r[2]), "=r"(r[3]) : "r"(addr));
}
__device__ __forceinline__ void mma16816(float* c, const uint32_t* a,
                                         uint32_t b0, uint32_t b1) {
    asm volatile("mma.sync.aligned.m16n8k16.row.col.f32.f16.f16.f32 "
                 "{%0,%1,%2,%3}, {%4,%5,%6,%7}, {%8,%9}, {%0,%1,%2,%3};"
                 : "+f"(c[0]), "+f"(c[1]), "+f"(c[2]), "+f"(c[3])
                 : "r"(a[0]), "r"(a[1]), "r"(a[2]), "r"(a[3]), "r"(b0), "r"(b1));
}
__device__ __forceinline__ void fma2(unsigned long long& a, unsigned long long x,
                                     unsigned long long w) {
    asm("fma.rn.f32x2 %0, %1, %2, %0;" : "+l"(a) : "l"(x), "l"(w));
}
__device__ __forceinline__ unsigned long long pack2(float v) {
    unsigned long long r;
    asm("mov.b64 %0, {%1, %1};" : "=l"(r) : "r"(__float_as_uint(v)));
    return r;
}

// ===========================================================================
// Kernel A: offset conv partials (32-ch groups), packed f32x2 math
// ===========================================================================
__global__ __launch_bounds__(128)
void offset_conv_part(const float* __restrict__ x,
                      const float* __restrict__ w_off) {
    __shared__ float sx[4][64];
    __shared__ __align__(16) float sw2[9 * 28];

    int cg = blockIdx.x & 7;
    int hs = (blockIdx.x >> 3) & 31;
    int b  = blockIdx.x >> 8;
    int h0 = hs << 1;
    int ty = threadIdx.x >> 6;
    int w  = threadIdx.x & 63;
    int h  = h0 + ty;

    if (threadIdx.x < 9) sw2[threadIdx.x * 28 + 27] = 0.f;

    unsigned long long acc2[14];
#pragma unroll
    for (int j = 0; j < 14; ++j) acc2[j] = 0ULL;

    const float* xb = x + (size_t)b * Cc * HW;
    int c0 = cg * CPG;

    for (int ci = 0; ci < CPG; ++ci) {
        int c = c0 + ci;
#pragma unroll
        for (int r = ty; r < 4; r += 2) {
            int yy = h0 - 1 + r;
            sx[r][w] = (yy >= 0 && yy < Hh) ? xb[(size_t)c * HW + yy * 64 + w] : 0.f;
        }
        for (int i = threadIdx.x; i < 243; i += 128) {
            int oc = i / 9, t = i - oc * 9;
            sw2[t * 28 + oc] = w_off[(size_t)oc * KTOT + c * 9 + t];
        }
        __syncthreads();

        float xv[9];
#pragma unroll
        for (int dy = 0; dy < 3; ++dy)
#pragma unroll
            for (int dx = 0; dx < 3; ++dx) {
                int xx = w - 1 + dx;
                xv[dy * 3 + dx] = (xx >= 0 && xx < Ww) ? sx[ty + dy][xx] : 0.f;
            }

#pragma unroll
        for (int t = 0; t < 9; ++t) {
            unsigned long long xp = pack2(xv[t]);
            const ulonglong2* wp = (const ulonglong2*)&sw2[t * 28];
#pragma unroll
            for (int j = 0; j < 7; ++j) {
                ulonglong2 w2 = wp[j];
                fma2(acc2[2 * j],     xp, w2.x);
                fma2(acc2[2 * j + 1], xp, w2.y);
            }
        }
        __syncthreads();
    }

    size_t outb = ((size_t)b * OCOFF) * HW + h * 64 + w;
#pragma unroll
    for (int j = 0; j < 14; ++j) {
        float lo = __uint_as_float((uint32_t)acc2[j]);
        float hi = __uint_as_float((uint32_t)(acc2[j] >> 32));
        int oc0 = 2 * j, oc1 = 2 * j + 1;
        g_part[cg][outb + (size_t)oc0 * HW] = lo;
        if (oc1 < OCOFF) g_part[cg][outb + (size_t)oc1 * HW] = hi;
    }
}

// ===========================================================================
// Kernel W: split weights into fp16 hi + fp16 residual planes
// ===========================================================================
__global__ void wprep_kernel(const float* __restrict__ weight) {
    int idx = blockIdx.x * 256 + threadIdx.x;
    if (idx >= Oo * KTOT) return;
    float wv = weight[idx];
    __half wh = __float2half_rn(wv);
    float whf = __half2float(wh);
    __half wl = __float2half_rn(wv - whf);
    g_AH[idx] = __half_as_ushort(wh);
    g_AL[idx] = __half_as_ushort(wl);
}

// ===========================================================================
// Kernel B: fused offset-reduce + deform-sample -> fp16 cols [k][n].
// 288 threads = 32 n x 9 kk. Params in registers; loop 256 channels;
// direct coalesced stores, no smem, no barriers.
// ===========================================================================
__global__ __launch_bounds__(288)
void build_cols_kernel(const float* __restrict__ x,
                       const float* __restrict__ b_off) {
    int tid = threadIdx.x;
    int n_l = tid & 31;
    int kk  = tid >> 5;                // 0..8
    int n0  = blockIdx.x * 32;
    int n   = n0 + n_l;
    int b   = n >> 12;
    int hw  = n & 4095;
    int h   = hw >> 6, w = hw & 63;

    // fused 8-way partial reduction (replaces offset_reduce kernel)
    size_t pbase = ((size_t)b * OCOFF) * HW + hw;
    float oy = b_off[kk], ox = b_off[9 + kk], ms = b_off[18 + kk];
#pragma unroll
    for (int g = 0; g < CSPLIT; ++g) {
        oy += g_part[g][pbase + (size_t)kk * HW];
        ox += g_part[g][pbase + (size_t)(9 + kk) * HW];
        ms += g_part[g][pbase + (size_t)(18 + kk) * HW];
    }
    float m = 1.f / (1.f + expf(-ms));

    float py = (float)(h - 1 + kk / 3) + oy;
    float px = (float)(w - 1 + kk % 3) + ox;
    float y0f = floorf(py), x0f = floorf(px);
    float wy = py - y0f, wx = px - x0f;
    int y0 = (int)y0f, x0 = (int)x0f;

    bool yv0 = (y0 >= 0) & (y0 < Hh);
    bool yv1 = (y0 + 1 >= 0) & (y0 + 1 < Hh);
    bool xv0 = (x0 >= 0) & (x0 < Ww);
    bool xv1 = (x0 + 1 >= 0) & (x0 + 1 < Ww);

    float w00 = m * (1.f - wy) * (1.f - wx) * (float)(yv0 & xv0);
    float w01 = m * (1.f - wy) * wx         * (float)(yv0 & xv1);
    float w10 = m * wy * (1.f - wx)         * (float)(yv1 & xv0);
    float w11 = m * wy * wx                 * (float)(yv1 & xv1);

    int y0c = min(max(y0, 0), Hh - 1);
    int y1c = min(max(y0 + 1, 0), Hh - 1);
    int x0c = min(max(x0, 0), Ww - 1);
    int x1c = min(max(x0 + 1, 0), Ww - 1);
    int o00 = y0c * 64 + x0c, o01 = y0c * 64 + x1c;
    int o10 = y1c * 64 + x0c, o11 = y1c * 64 + x1c;

    const float* xb = x + (size_t)b * Cc * HW;

#pragma unroll 1
    for (int c0 = 0; c0 < Cc; c0 += 8) {
        float val[8];
#pragma unroll
        for (int cl = 0; cl < 8; ++cl) {
            const float* xc = xb + (size_t)(c0 + cl) * HW;
            val[cl] = xc[o00] * w00 + xc[o01] * w01
                    + xc[o10] * w10 + xc[o11] * w11;
        }
#pragma unroll
        for (int cl = 0; cl < 8; ++cl) {
            size_t off = (size_t)((c0 + cl) * 9 + kk) * NTOT + n;
            g_cols[off] = __half_as_ushort(__float2half_rn(val[cl]));
        }
    }
}

// ===========================================================================
// Kernel C: HMMA 2-chain fp16 GEMM.  M=256 (whole O) x N=128, K=2304/chain.
// out = (AH + AL) x B_fp16;  A exact (hi+residual), B single fp16 plane.
// 512 threads, 16 warps (8M x 2N), 2-stage cp.async, K-chunk 64.
// ===========================================================================
#define AT 32768                 /* 256 rows x 128B, per A plane */
#define B_OFF 65536              /* B plane: 64 k-rows x 256B   */
#define STAGEB 81920
#define GSM    163840
#define NCHUNK 36

__device__ __forceinline__ void load_chunk(uint32_t sbu, uint32_t stoff, int chunk,
                                           int bn, int tid) {
    int kw = chunk * 64;
    uint32_t base = sbu + stoff;
    int r = tid >> 3, q = tid & 7;
    // A: 256 rows x 128B per plane
#pragma unroll
    for (int rr = 0; rr < 4; ++rr) {
        int row = r + rr * 64;
        uint32_t o = swz((uint32_t)(row * 128 + q * 16));
        cp16(base + o,      &g_AH[(size_t)row * KTOT + kw + q * 8]);
        cp16(base + AT + o, &g_AL[(size_t)row * KTOT + kw + q * 8]);
    }
    // B: 64 k-rows x 256B (n-contiguous)
    {
        int krow = r;                 // 0..63
        const uint16_t* s = &g_cols[(size_t)(kw + krow) * NTOT + bn];
        uint32_t o0 = swz2((uint32_t)(krow * 256 + q * 16));
        uint32_t o1 = swz2((uint32_t)(krow * 256 + (q + 8) * 16));
        cp16(base + B_OFF + o0, s + q * 8);
        cp16(base + B_OFF + o1, s + (q + 8) * 8);
    }
}

__global__ __launch_bounds__(512, 1)
void gemm_mma_kernel(const float* __restrict__ bias,
                     const float* __restrict__ gamma,
                     const float* __restrict__ beta,
                     const float* __restrict__ rmean,
                     const float* __restrict__ rvar,
                     float* __restrict__ out) {
    extern __shared__ char smc[];
    uint32_t sbu = smem_u32(smc);
    int tid  = threadIdx.x;
    int lane = tid & 31;
    int wid  = tid >> 5;
    int bn = blockIdx.x * 128;
    int warp_m = wid & 7;
    int warp_n = wid >> 3;

    int mi   = lane >> 3;
    int mrow = lane & 7;
    int rbit = ((mi & 1) << 3) + mrow;
    int cbit = (mi >> 1) << 4;
    int klane = ((mi >> 1) << 3) + mrow;
    int nlane = (mi & 1) << 3;

    float acc[2][8][4];
#pragma unroll
    for (int a = 0; a < 2; ++a)
#pragma unroll
        for (int b2 = 0; b2 < 8; ++b2)
#pragma unroll
            for (int c2 = 0; c2 < 4; ++c2) acc[a][b2][c2] = 0.f;

    load_chunk(sbu, 0,      0, bn, tid); CP_COMMIT();
    load_chunk(sbu, STAGEB, 1, bn, tid); CP_COMMIT();

    int arow0 = warp_m * 32;
    int brow0 = warp_n * 64;

    for (int i = 0; i < NCHUNK; ++i) {
        int st = i & 1;
        CP_WAIT1();
        __syncthreads();

        uint32_t base = sbu + st * STAGEB;
#pragma unroll
        for (int ks = 0; ks < 4; ++ks) {
            int kb = ks * 32;
            uint32_t boffs[4], aoffs[2];
#pragma unroll
            for (int ng = 0; ng < 4; ++ng)
                boffs[ng] = swz2((uint32_t)((ks * 16 + klane) * 256
                                 + (brow0 + ng * 16 + nlane) * 2));
#pragma unroll
            for (int mt = 0; mt < 2; ++mt)
                aoffs[mt] = swz((uint32_t)((arow0 + mt * 16 + rbit) * 128 + kb + cbit));

            uint32_t bq[4][4], ah[2][4];
#pragma unroll
            for (int ng = 0; ng < 4; ++ng) ldsm4t(bq[ng], base + B_OFF + boffs[ng]);
#pragma unroll
            for (int mt = 0; mt < 2; ++mt) ldsm4(ah[mt], base + aoffs[mt]);

            // AH x B
#pragma unroll
            for (int mt = 0; mt < 2; ++mt)
#pragma unroll
                for (int ng = 0; ng < 4; ++ng) {
                    mma16816(acc[mt][ng * 2 + 0], ah[mt], bq[ng][0], bq[ng][2]);
                    mma16816(acc[mt][ng * 2 + 1], ah[mt], bq[ng][1], bq[ng][3]);
                }
            // AL x B
#pragma unroll
            for (int mt = 0; mt < 2; ++mt) {
                uint32_t al[4];
                ldsm4(al, base + AT + aoffs[mt]);
#pragma unroll
                for (int ng = 0; ng < 4; ++ng) {
                    mma16816(acc[mt][ng * 2 + 0], al, bq[ng][0], bq[ng][2]);
                    mma16816(acc[mt][ng * 2 + 1], al, bq[ng][1], bq[ng][3]);
                }
            }
        }
        __syncthreads();
        if (i + 2 < NCHUNK) load_chunk(sbu, st * STAGEB, i + 2, bn, tid);
        CP_COMMIT();
    }

    // epilogue: BN + bias + ReLU, float2 stores
    int nbase = bn + warp_n * 64;
#pragma unroll
    for (int mt = 0; mt < 2; ++mt) {
        int o0 = warp_m * 32 + mt * 16 + (lane >> 2);
        int o1 = o0 + 8;
        float inv0 = gamma[o0] * rsqrtf(rvar[o0] + 1e-5f);
        float sh0  = beta[o0] - rmean[o0] * inv0 + bias[o0] * inv0;
        float inv1 = gamma[o1] * rsqrtf(rvar[o1] + 1e-5f);
        float sh1  = beta[o1] - rmean[o1] * inv1 + bias[o1] * inv1;
#pragma unroll
        for (int nt = 0; nt < 8; ++nt) {
            int n = nbase + nt * 8 + ((lane & 3) << 1);
            int bimg = n >> 12;
            int hw   = n & 4095;
            float2 v0, v1;
            v0.x = fmaxf(fmaf(acc[mt][nt][0], inv0, sh0), 0.f);
            v0.y = fmaxf(fmaf(acc[mt][nt][1], inv0, sh0), 0.f);
            v1.x = fmaxf(fmaf(acc[mt][nt][2], inv1, sh1), 0.f);
            v1.y = fmaxf(fmaf(acc[mt][nt][3], inv1, sh1), 0.f);
            *(float2*)&out[(((size_t)(bimg * Oo + o0)) << 12) + hw] = v0;
            *(float2*)&out[(((size_t)(bimg * Oo + o1)) << 12) + hw] = v1;
        }
    }
}

// ===========================================================================
extern "C" void kernel_launch(void* const* d_in, const int* in_sizes, int n_in,
                              void* d_out, int out_size) {
    const float* x      = (const float*)d_in[0];
    const float* w_off  = (const float*)d_in[1];
    const float* b_off  = (const float*)d_in[2];
    const float* weight = (const float*)d_in[3];
    const float* bias   = (const float*)d_in[4];
    const float* gamma  = (const float*)d_in[5];
    const float* beta   = (const float*)d_in[6];
    const float* rmean  = (const float*)d_in[7];
    const float* rvar   = (const float*)d_in[8];
    float* out = (float*)d_out;

    cudaFuncSetAttribute(gemm_mma_kernel,
                         cudaFuncAttributeMaxDynamicSharedMemorySize, GSM);

    wprep_kernel<<<(Oo * KTOT + 255) / 256, 256>>>(weight);
    offset_conv_part<<<Bb * 32 * CSPLIT, 128>>>(x, w_off);
    build_cols_kernel<<<NTOT / 32, 288>>>(x, b_off);

    gemm_mma_kernel<<<NTOT / 128, 512, GSM>>>(bias, gamma, beta, rmean, rvar, out);
}

// round 9
// speedup vs baseline: 1.5885x; 1.1717x over previous
#include <cuda_runtime.h>
#include <cuda_fp16.h>
#include <math.h>
#include <stdint.h>

#define Bb   8
#define Cc   256
#define Hh   64
#define Ww   64
#define Oo   256
#define HW   4096
#define OCOFF 27
#define KTOT 2304            /* K = C*9 */
#define NTOT 32768           /* B*H*W */
#define CSPLIT 8
#define CPG (Cc / CSPLIT)

// ---------------- scratch (__device__ globals) ------------------------------
__device__ float    g_part[CSPLIT][Bb * OCOFF * HW];   // offset-conv partials
__device__ uint16_t g_cols[(size_t)KTOT * NTOT];       // fp16 cols, [k][n]
__device__ uint16_t g_A[Oo * KTOT];                    // weight fp16, [o][k]

// ---------------- helpers ----------------------------------------------------
__device__ __forceinline__ uint32_t smem_u32(const void* p) {
    uint32_t a;
    asm("{ .reg .u64 t; cvta.to.shared.u64 t, %1; cvt.u32.u64 %0, t; }" : "=r"(a) : "l"(p));
    return a;
}
__device__ __forceinline__ uint32_t swz(uint32_t off)  { return off ^ ((off >> 3) & 0x70); }
__device__ __forceinline__ uint32_t swz2(uint32_t off) { return off ^ ((off >> 4) & 0x70); }

__device__ __forceinline__ void cp16(uint32_t dst, const void* src) {
    asm volatile("cp.async.cg.shared.global [%0], [%1], 16;" :: "r"(dst), "l"(src));
}
#define CP_COMMIT() asm volatile("cp.async.commit_group;" ::: "memory")
#define CP_WAIT2()  asm volatile("cp.async.wait_group 2;" ::: "memory")

__device__ __forceinline__ void ldsm4(uint32_t* r, uint32_t addr) {
    asm volatile("ldmatrix.sync.aligned.m8n8.x4.shared.b16 {%0,%1,%2,%3}, [%4];"
                 : "=r"(r[0]), "=r"(r[1]), "=r"(r[2]), "=r"(r[3]) : "r"(addr));
}
__device__ __forceinline__ void ldsm4t(uint32_t* r, uint32_t addr) {
    asm volatile("ldmatrix.sync.aligned.m8n8.x4.trans.shared.b16 {%0,%1,%2,%3}, [%4];"
                 : "=r"(r[0]), "=r"(r[1]), "=r"(r[2]), "=r"(r[3]) : "r"(addr));
}
__device__ __forceinline__ void mma16816(float* c, const uint32_t* a,
                                         uint32_t b0, uint32_t b1) {
    asm volatile("mma.sync.aligned.m16n8k16.row.col.f32.f16.f16.f32 "
                 "{%0,%1,%2,%3}, {%4,%5,%6,%7}, {%8,%9}, {%0,%1,%2,%3};"
                 : "+f"(c[0]), "+f"(c[1]), "+f"(c[2]), "+f"(c[3])
                 : "r"(a[0]), "r"(a[1]), "r"(a[2]), "r"(a[3]), "r"(b0), "r"(b1));
}
__device__ __forceinline__ void fma2(unsigned long long& a, unsigned long long x,
                                     unsigned long long w) {
    asm("fma.rn.f32x2 %0, %1, %2, %0;" : "+l"(a) : "l"(x), "l"(w));
}
__device__ __forceinline__ unsigned long long pack2(float v) {
    unsigned long long r;
    asm("mov.b64 %0, {%1, %1};" : "=l"(r) : "r"(__float_as_uint(v)));
    return r;
}

// ===========================================================================
// Kernel A: offset conv partials (32-ch groups), packed f32x2 math
// 256 threads = 4 rows x 64 w; grid = 8(b) * 16(hslab) * 8(cgroup)
// ===========================================================================
__global__ __launch_bounds__(256)
void offset_conv_part(const float* __restrict__ x,
                      const float* __restrict__ w_off) {
    __shared__ float sx[6][64];
    __shared__ __align__(16) float sw2[9 * 28];

    int cg = blockIdx.x & 7;
    int hs = (blockIdx.x >> 3) & 15;
    int b  = blockIdx.x >> 7;
    int h0 = hs << 2;
    int ty = threadIdx.x >> 6;       // 0..3
    int w  = threadIdx.x & 63;
    int h  = h0 + ty;

    if (threadIdx.x < 9) sw2[threadIdx.x * 28 + 27] = 0.f;

    unsigned long long acc2[14];
#pragma unroll
    for (int j = 0; j < 14; ++j) acc2[j] = 0ULL;

    const float* xb = x + (size_t)b * Cc * HW;
    int c0 = cg * CPG;

    for (int ci = 0; ci < CPG; ++ci) {
        int c = c0 + ci;
#pragma unroll
        for (int r = ty; r < 6; r += 4) {
            int yy = h0 - 1 + r;
            sx[r][w] = (yy >= 0 && yy < Hh) ? xb[(size_t)c * HW + yy * 64 + w] : 0.f;
        }
        if (threadIdx.x < 243) {
            int oc = threadIdx.x / 9, t = threadIdx.x - oc * 9;
            sw2[t * 28 + oc] = w_off[(size_t)oc * KTOT + c * 9 + t];
        }
        __syncthreads();

        float xv[9];
#pragma unroll
        for (int dy = 0; dy < 3; ++dy)
#pragma unroll
            for (int dx = 0; dx < 3; ++dx) {
                int xx = w - 1 + dx;
                xv[dy * 3 + dx] = (xx >= 0 && xx < Ww) ? sx[ty + dy][xx] : 0.f;
            }

#pragma unroll
        for (int t = 0; t < 9; ++t) {
            unsigned long long xp = pack2(xv[t]);
            const ulonglong2* wp = (const ulonglong2*)&sw2[t * 28];
#pragma unroll
            for (int j = 0; j < 7; ++j) {
                ulonglong2 w2 = wp[j];
                fma2(acc2[2 * j],     xp, w2.x);
                fma2(acc2[2 * j + 1], xp, w2.y);
            }
        }
        __syncthreads();
    }

    size_t outb = ((size_t)b * OCOFF) * HW + h * 64 + w;
#pragma unroll
    for (int j = 0; j < 14; ++j) {
        float lo = __uint_as_float((uint32_t)acc2[j]);
        float hi = __uint_as_float((uint32_t)(acc2[j] >> 32));
        int oc0 = 2 * j, oc1 = 2 * j + 1;
        g_part[cg][outb + (size_t)oc0 * HW] = lo;
        if (oc1 < OCOFF) g_part[cg][outb + (size_t)oc1 * HW] = hi;
    }
}

// ===========================================================================
// Kernel W: weights -> fp16 plane
// ===========================================================================
__global__ void wprep_kernel(const float* __restrict__ weight) {
    int idx = blockIdx.x * 256 + threadIdx.x;
    if (idx >= Oo * KTOT) return;
    g_A[idx] = __half_as_ushort(__float2half_rn(weight[idx]));
}

// ===========================================================================
// Kernel B: fused offset-reduce + deform-sample -> fp16 cols [k][n].
// 288 threads = 32 n x 9 kk; params in registers; direct coalesced stores.
// ===========================================================================
__global__ __launch_bounds__(288)
void build_cols_kernel(const float* __restrict__ x,
                       const float* __restrict__ b_off) {
    int tid = threadIdx.x;
    int n_l = tid & 31;
    int kk  = tid >> 5;                // 0..8
    int n0  = blockIdx.x * 32;
    int n   = n0 + n_l;
    int b   = n >> 12;
    int hw  = n & 4095;
    int h   = hw >> 6, w = hw & 63;

    size_t pbase = ((size_t)b * OCOFF) * HW + hw;
    float oy = b_off[kk], ox = b_off[9 + kk], ms = b_off[18 + kk];
#pragma unroll
    for (int g = 0; g < CSPLIT; ++g) {
        oy += g_part[g][pbase + (size_t)kk * HW];
        ox += g_part[g][pbase + (size_t)(9 + kk) * HW];
        ms += g_part[g][pbase + (size_t)(18 + kk) * HW];
    }
    float m = 1.f / (1.f + expf(-ms));

    float py = (float)(h - 1 + kk / 3) + oy;
    float px = (float)(w - 1 + kk % 3) + ox;
    float y0f = floorf(py), x0f = floorf(px);
    float wy = py - y0f, wx = px - x0f;
    int y0 = (int)y0f, x0 = (int)x0f;

    bool yv0 = (y0 >= 0) & (y0 < Hh);
    bool yv1 = (y0 + 1 >= 0) & (y0 + 1 < Hh);
    bool xv0 = (x0 >= 0) & (x0 < Ww);
    bool xv1 = (x0 + 1 >= 0) & (x0 + 1 < Ww);

    float w00 = m * (1.f - wy) * (1.f - wx) * (float)(yv0 & xv0);
    float w01 = m * (1.f - wy) * wx         * (float)(yv0 & xv1);
    float w10 = m * wy * (1.f - wx)         * (float)(yv1 & xv0);
    float w11 = m * wy * wx                 * (float)(yv1 & xv1);

    int y0c = min(max(y0, 0), Hh - 1);
    int y1c = min(max(y0 + 1, 0), Hh - 1);
    int x0c = min(max(x0, 0), Ww - 1);
    int x1c = min(max(x0 + 1, 0), Ww - 1);
    int o00 = y0c * 64 + x0c, o01 = y0c * 64 + x1c;
    int o10 = y1c * 64 + x0c, o11 = y1c * 64 + x1c;

    const float* xb = x + (size_t)b * Cc * HW;

#pragma unroll 1
    for (int c0 = 0; c0 < Cc; c0 += 8) {
        float val[8];
#pragma unroll
        for (int cl = 0; cl < 8; ++cl) {
            const float* xc = xb + (size_t)(c0 + cl) * HW;
            val[cl] = xc[o00] * w00 + xc[o01] * w01
                    + xc[o10] * w10 + xc[o11] * w11;
        }
#pragma unroll
        for (int cl = 0; cl < 8; ++cl) {
            size_t off = (size_t)((c0 + cl) * 9 + kk) * NTOT + n;
            g_cols[off] = __half_as_ushort(__float2half_rn(val[cl]));
        }
    }
}

// ===========================================================================
// Kernel C: single-chain fp16 HMMA GEMM.  M=256 x N=128, K=2304.
// 512 threads, 16 warps (4M x 4N, warp tile 64x32), 4-stage cp.async,
// K-chunk 64.  Fused bias+BN+ReLU epilogue.
// ===========================================================================
#define B_OFF  32768             /* A: 256 rows x 128B = 32KB, then B */
#define STAGEB 49152             /* + B: 64 k-rows x 256B = 16KB */
#define GSM    196608            /* 4 stages */
#define NCHUNK 36

__device__ __forceinline__ void load_chunk(uint32_t sbu, uint32_t stoff, int chunk,
                                           int bn, int tid) {
    int kw = chunk * 64;
    uint32_t base = sbu + stoff;
    int r = tid >> 3, q = tid & 7;
    // A: 256 rows x 128B
#pragma unroll
    for (int rr = 0; rr < 4; ++rr) {
        int row = r + rr * 64;
        uint32_t o = swz((uint32_t)(row * 128 + q * 16));
        cp16(base + o, &g_A[(size_t)row * KTOT + kw + q * 8]);
    }
    // B: 64 k-rows x 256B (n-contiguous)
    {
        const uint16_t* s = &g_cols[(size_t)(kw + r) * NTOT + bn];
        cp16(base + B_OFF + swz2((uint32_t)(r * 256 + q * 16)),       s + q * 8);
        cp16(base + B_OFF + swz2((uint32_t)(r * 256 + (q + 8) * 16)), s + (q + 8) * 8);
    }
}

__global__ __launch_bounds__(512, 1)
void gemm_mma_kernel(const float* __restrict__ bias,
                     const float* __restrict__ gamma,
                     const float* __restrict__ beta,
                     const float* __restrict__ rmean,
                     const float* __restrict__ rvar,
                     float* __restrict__ out) {
    extern __shared__ char smc[];
    uint32_t sbu = smem_u32(smc);
    int tid  = threadIdx.x;
    int lane = tid & 31;
    int wid  = tid >> 5;
    int bn = blockIdx.x * 128;
    int warp_m = wid & 3;                 // 4 warps along M (64 rows each)
    int warp_n = wid >> 2;                // 4 warps along N (32 cols each)

    int mi   = lane >> 3;
    int mrow = lane & 7;
    int rbit = ((mi & 1) << 3) + mrow;
    int cbit = (mi >> 1) << 4;
    int klane = ((mi >> 1) << 3) + mrow;
    int nlane = (mi & 1) << 3;

    float acc[4][4][4];
#pragma unroll
    for (int a = 0; a < 4; ++a)
#pragma unroll
        for (int b2 = 0; b2 < 4; ++b2)
#pragma unroll
            for (int c2 = 0; c2 < 4; ++c2) acc[a][b2][c2] = 0.f;

    load_chunk(sbu, 0 * STAGEB, 0, bn, tid); CP_COMMIT();
    load_chunk(sbu, 1 * STAGEB, 1, bn, tid); CP_COMMIT();
    load_chunk(sbu, 2 * STAGEB, 2, bn, tid); CP_COMMIT();

    int arow0 = warp_m * 64;
    int brow0 = warp_n * 32;

    for (int i = 0; i < NCHUNK; ++i) {
        int st = i & 3;
        CP_WAIT2();
        __syncthreads();

        if (i + 3 < NCHUNK)
            load_chunk(sbu, ((i + 3) & 3) * STAGEB, i + 3, bn, tid);
        CP_COMMIT();

        uint32_t base = sbu + st * STAGEB;
#pragma unroll
        for (int ks = 0; ks < 4; ++ks) {
            int kb = ks * 32;
            uint32_t bq[2][4], af[4][4];
#pragma unroll
            for (int ng = 0; ng < 2; ++ng)
                ldsm4t(bq[ng], base + B_OFF +
                       swz2((uint32_t)((ks * 16 + klane) * 256
                            + (brow0 + ng * 16 + nlane) * 2)));
#pragma unroll
            for (int mt = 0; mt < 4; ++mt)
                ldsm4(af[mt], base +
                      swz((uint32_t)((arow0 + mt * 16 + rbit) * 128 + kb + cbit)));

#pragma unroll
            for (int mt = 0; mt < 4; ++mt)
#pragma unroll
                for (int ng = 0; ng < 2; ++ng) {
                    mma16816(acc[mt][ng * 2 + 0], af[mt], bq[ng][0], bq[ng][2]);
                    mma16816(acc[mt][ng * 2 + 1], af[mt], bq[ng][1], bq[ng][3]);
                }
        }
        __syncthreads();
    }

    // epilogue: BN + bias + ReLU, float2 stores
    int nbase = bn + warp_n * 32;
#pragma unroll
    for (int mt = 0; mt < 4; ++mt) {
        int o0 = warp_m * 64 + mt * 16 + (lane >> 2);
        int o1 = o0 + 8;
        float inv0 = gamma[o0] * rsqrtf(rvar[o0] + 1e-5f);
        float sh0  = beta[o0] - rmean[o0] * inv0 + bias[o0] * inv0;
        float inv1 = gamma[o1] * rsqrtf(rvar[o1] + 1e-5f);
        float sh1  = beta[o1] - rmean[o1] * inv1 + bias[o1] * inv1;
#pragma unroll
        for (int nt = 0; nt < 4; ++nt) {
            int n = nbase + nt * 8 + ((lane & 3) << 1);
            int bimg = n >> 12;
            int hw   = n & 4095;
            float2 v0, v1;
            v0.x = fmaxf(fmaf(acc[mt][nt][0], inv0, sh0), 0.f);
            v0.y = fmaxf(fmaf(acc[mt][nt][1], inv0, sh0), 0.f);
            v1.x = fmaxf(fmaf(acc[mt][nt][2], inv1, sh1), 0.f);
            v1.y = fmaxf(fmaf(acc[mt][nt][3], inv1, sh1), 0.f);
            *(float2*)&out[(((size_t)(bimg * Oo + o0)) << 12) + hw] = v0;
            *(float2*)&out[(((size_t)(bimg * Oo + o1)) << 12) + hw] = v1;
        }
    }
}

// ===========================================================================
extern "C" void kernel_launch(void* const* d_in, const int* in_sizes, int n_in,
                              void* d_out, int out_size) {
    const float* x      = (const float*)d_in[0];
    const float* w_off  = (const float*)d_in[1];
    const float* b_off  = (const float*)d_in[2];
    const float* weight = (const float*)d_in[3];
    const float* bias   = (const float*)d_in[4];
    const float* gamma  = (const float*)d_in[5];
    const float* beta   = (const float*)d_in[6];
    const float* rmean  = (const float*)d_in[7];
    const float* rvar   = (const float*)d_in[8];
    float* out = (float*)d_out;

    cudaFuncSetAttribute(gemm_mma_kernel,
                         cudaFuncAttributeMaxDynamicSharedMemorySize, GSM);

    wprep_kernel<<<(Oo * KTOT + 255) / 256, 256>>>(weight);
    offset_conv_part<<<Bb * 16 * CSPLIT, 256>>>(x, w_off);
    build_cols_kernel<<<NTOT / 32, 288>>>(x, b_off);

    gemm_mma_kernel<<<NTOT / 128, 512, GSM>>>(bias, gamma, beta, rmean, rvar, out);
}

// round 10
// speedup vs baseline: 1.7573x; 1.1062x over previous
#include <cuda_runtime.h>
#include <cuda_fp16.h>
#include <math.h>
#include <stdint.h>

#define Bb   8
#define Cc   256
#define Hh   64
#define Ww   64
#define Oo   256
#define HW   4096
#define OCOFF 27
#define KTOT 2304            /* K = C*9 */
#define NTOT 32768           /* B*H*W */
#define CSPLIT 8
#define CPG (Cc / CSPLIT)

// ---------------- scratch (__device__ globals) ------------------------------
__device__ float    g_part[CSPLIT][Bb * OCOFF * HW];   // offset-conv partials
__device__ uint16_t g_cols[(size_t)KTOT * NTOT];       // fp16 cols, [k][n]
__device__ uint16_t g_A[Oo * KTOT];                    // weight fp16, [o][k]

// ---------------- helpers ----------------------------------------------------
__device__ __forceinline__ uint32_t smem_u32(const void* p) {
    uint32_t a;
    asm("{ .reg .u64 t; cvta.to.shared.u64 t, %1; cvt.u32.u64 %0, t; }" : "=r"(a) : "l"(p));
    return a;
}
__device__ __forceinline__ uint32_t swz(uint32_t off)  { return off ^ ((off >> 3) & 0x70); }
__device__ __forceinline__ uint32_t swz2(uint32_t off) { return off ^ ((off >> 4) & 0x70); }

__device__ __forceinline__ void cp16(uint32_t dst, const void* src) {
    asm volatile("cp.async.cg.shared.global [%0], [%1], 16;" :: "r"(dst), "l"(src));
}
#define CP_COMMIT() asm volatile("cp.async.commit_group;" ::: "memory")
#define CP_WAIT1()  asm volatile("cp.async.wait_group 1;" ::: "memory")

__device__ __forceinline__ void ldsm4(uint32_t* r, uint32_t addr) {
    asm volatile("ldmatrix.sync.aligned.m8n8.x4.shared.b16 {%0,%1,%2,%3}, [%4];"
                 : "=r"(r[0]), "=r"(r[1]), "=r"(r[2]), "=r"(r[3]) : "r"(addr));
}
__device__ __forceinline__ void ldsm4t(uint32_t* r, uint32_t addr) {
    asm volatile("ldmatrix.sync.aligned.m8n8.x4.trans.shared.b16 {%0,%1,%2,%3}, [%4];"
                 : "=r"(r[0]), "=r"(r[1]), "=r"(r[2]), "=r"(r[3]) : "r"(addr));
}
__device__ __forceinline__ void mma16816(float* c, const uint32_t* a,
                                         uint32_t b0, uint32_t b1) {
    asm volatile("mma.sync.aligned.m16n8k16.row.col.f32.f16.f16.f32 "
                 "{%0,%1,%2,%3}, {%4,%5,%6,%7}, {%8,%9}, {%0,%1,%2,%3};"
                 : "+f"(c[0]), "+f"(c[1]), "+f"(c[2]), "+f"(c[3])
                 : "r"(a[0]), "r"(a[1]), "r"(a[2]), "r"(a[3]), "r"(b0), "r"(b1));
}
__device__ __forceinline__ void fma2(unsigned long long& a, unsigned long long x,
                                     unsigned long long w) {
    asm("fma.rn.f32x2 %0, %1, %2, %0;" : "+l"(a) : "l"(x), "l"(w));
}
__device__ __forceinline__ unsigned long long pack2(float v) {
    unsigned long long r;
    asm("mov.b64 %0, {%1, %1};" : "=l"(r) : "r"(__float_as_uint(v)));
    return r;
}

// ===========================================================================
// Kernel A: offset conv partials (32-ch groups), packed f32x2 math.
// Weights for the whole c-group staged in smem ONCE; x rows double-buffered
// via register prefetch -> 1 barrier per channel.
// 256 threads = 4 rows x 64 w; grid = 8(b) * 16(hslab) * 8(cgroup)
// ===========================================================================
__global__ __launch_bounds__(256)
void offset_conv_part(const float* __restrict__ x,
                      const float* __restrict__ w_off) {
    __shared__ __align__(16) float swt[CPG * 252];   // [ci][t][oc pad 28]
    __shared__ float sx[2][6][64];

    int cg = blockIdx.x & 7;
    int hs = (blockIdx.x >> 3) & 15;
    int b  = blockIdx.x >> 7;
    int h0 = hs << 2;
    int tid = threadIdx.x;
    int ty = tid >> 6;               // 0..3
    int w  = tid & 63;
    int h  = h0 + ty;
    int c0 = cg * CPG;

    const float* xb = x + (size_t)b * Cc * HW;

    // one-time weight stage: 27 segments of 288 contiguous floats
    for (int i = tid; i < 288; i += 256) swt[i * 28 + 27] = 0.f;
    for (int i = tid; i < OCOFF * 288; i += 256) {
        int oc  = i / 288;
        int rem = i - oc * 288;                 // ci*9 + t
        int ci  = rem / 9, t = rem - ci * 9;
        swt[ci * 252 + t * 28 + oc] = w_off[(size_t)oc * KTOT + c0 * 9 + rem];
    }

    bool ldr = tid < 96;
    int lrow = tid >> 4;             // 0..5
    int lseg = tid & 15;             // 0..15
    int yy   = h0 - 1 + lrow;
    bool yok = (yy >= 0) & (yy < Hh);

    // prologue: stage channel 0 rows
    if (ldr) {
        float4 v = make_float4(0.f, 0.f, 0.f, 0.f);
        if (yok) v = *(const float4*)&xb[(size_t)c0 * HW + yy * 64 + lseg * 4];
        *(float4*)&sx[0][lrow][lseg * 4] = v;
    }
    __syncthreads();

    unsigned long long acc2[14];
#pragma unroll
    for (int j = 0; j < 14; ++j) acc2[j] = 0ULL;

    for (int ci = 0; ci < CPG; ++ci) {
        // prefetch next channel rows into registers (LDG overlaps compute)
        float4 nv = make_float4(0.f, 0.f, 0.f, 0.f);
        if (ci + 1 < CPG && ldr && yok)
            nv = *(const float4*)&xb[(size_t)(c0 + ci + 1) * HW + yy * 64 + lseg * 4];

        const float (*cur)[64] = sx[ci & 1];
        float xv[9];
#pragma unroll
        for (int dy = 0; dy < 3; ++dy)
#pragma unroll
            for (int dx = 0; dx < 3; ++dx) {
                int xx = w - 1 + dx;
                xv[dy * 3 + dx] = (xx >= 0 && xx < Ww) ? cur[ty + dy][xx] : 0.f;
            }

#pragma unroll
        for (int t = 0; t < 9; ++t) {
            unsigned long long xp = pack2(xv[t]);
            const ulonglong2* wp = (const ulonglong2*)&swt[ci * 252 + t * 28];
#pragma unroll
            for (int j = 0; j < 7; ++j) {
                ulonglong2 w2 = wp[j];
                fma2(acc2[2 * j],     xp, w2.x);
                fma2(acc2[2 * j + 1], xp, w2.y);
            }
        }

        if (ci + 1 < CPG && ldr)
            *(float4*)&sx[(ci + 1) & 1][lrow][lseg * 4] = nv;
        __syncthreads();
    }

    size_t outb = ((size_t)b * OCOFF) * HW + h * 64 + w;
#pragma unroll
    for (int j = 0; j < 14; ++j) {
        float lo = __uint_as_float((uint32_t)acc2[j]);
        float hi = __uint_as_float((uint32_t)(acc2[j] >> 32));
        int oc0 = 2 * j, oc1 = 2 * j + 1;
        g_part[cg][outb + (size_t)oc0 * HW] = lo;
        if (oc1 < OCOFF) g_part[cg][outb + (size_t)oc1 * HW] = hi;
    }
}

// ===========================================================================
// Kernel W: weights -> fp16 plane
// ===========================================================================
__global__ void wprep_kernel(const float* __restrict__ weight) {
    int idx = blockIdx.x * 256 + threadIdx.x;
    if (idx >= Oo * KTOT) return;
    g_A[idx] = __half_as_ushort(__float2half_rn(weight[idx]));
}

// ===========================================================================
// Kernel B: fused offset-reduce + deform-sample -> fp16 cols [k][n].
// 288 threads = 32 n x 9 kk; params in registers; direct coalesced stores.
// ===========================================================================
__global__ __launch_bounds__(288)
void build_cols_kernel(const float* __restrict__ x,
                       const float* __restrict__ b_off) {
    int tid = threadIdx.x;
    int n_l = tid & 31;
    int kk  = tid >> 5;                // 0..8
    int n0  = blockIdx.x * 32;
    int n   = n0 + n_l;
    int b   = n >> 12;
    int hw  = n & 4095;
    int h   = hw >> 6, w = hw & 63;

    size_t pbase = ((size_t)b * OCOFF) * HW + hw;
    float oy = b_off[kk], ox = b_off[9 + kk], ms = b_off[18 + kk];
#pragma unroll
    for (int g = 0; g < CSPLIT; ++g) {
        oy += g_part[g][pbase + (size_t)kk * HW];
        ox += g_part[g][pbase + (size_t)(9 + kk) * HW];
        ms += g_part[g][pbase + (size_t)(18 + kk) * HW];
    }
    float m = 1.f / (1.f + expf(-ms));

    float py = (float)(h - 1 + kk / 3) + oy;
    float px = (float)(w - 1 + kk % 3) + ox;
    float y0f = floorf(py), x0f = floorf(px);
    float wy = py - y0f, wx = px - x0f;
    int y0 = (int)y0f, x0 = (int)x0f;

    bool yv0 = (y0 >= 0) & (y0 < Hh);
    bool yv1 = (y0 + 1 >= 0) & (y0 + 1 < Hh);
    bool xv0 = (x0 >= 0) & (x0 < Ww);
    bool xv1 = (x0 + 1 >= 0) & (x0 + 1 < Ww);

    float w00 = m * (1.f - wy) * (1.f - wx) * (float)(yv0 & xv0);
    float w01 = m * (1.f - wy) * wx         * (float)(yv0 & xv1);
    float w10 = m * wy * (1.f - wx)         * (float)(yv1 & xv0);
    float w11 = m * wy * wx                 * (float)(yv1 & xv1);

    int y0c = min(max(y0, 0), Hh - 1);
    int y1c = min(max(y0 + 1, 0), Hh - 1);
    int x0c = min(max(x0, 0), Ww - 1);
    int x1c = min(max(x0 + 1, 0), Ww - 1);
    int o00 = y0c * 64 + x0c, o01 = y0c * 64 + x1c;
    int o10 = y1c * 64 + x0c, o11 = y1c * 64 + x1c;

    const float* xb = x + (size_t)b * Cc * HW;

#pragma unroll 1
    for (int c0 = 0; c0 < Cc; c0 += 8) {
        float val[8];
#pragma unroll
        for (int cl = 0; cl < 8; ++cl) {
            const float* xc = xb + (size_t)(c0 + cl) * HW;
            val[cl] = xc[o00] * w00 + xc[o01] * w01
                    + xc[o10] * w10 + xc[o11] * w11;
        }
#pragma unroll
        for (int cl = 0; cl < 8; ++cl) {
            size_t off = (size_t)((c0 + cl) * 9 + kk) * NTOT + n;
            g_cols[off] = __half_as_ushort(__float2half_rn(val[cl]));
        }
    }
}

// ===========================================================================
// Kernel C: single-chain fp16 HMMA GEMM.  M=128 x N=128 tiles, K=2304.
// 256 threads, 8 warps (2M x 4N, warp tile 64x32), 3-stage cp.async,
// 2 CTAs/SM for cross-CTA latency hiding.  Fused bias+BN+ReLU epilogue.
// ===========================================================================
#define B_OFF  16384             /* A: 128 rows x 128B = 16KB, then B 16KB */
#define STAGEB 32768
#define GSM    98304             /* 3 stages */
#define NCHUNK 36

__device__ __forceinline__ void load_chunk(uint32_t sbu, uint32_t stoff, int chunk,
                                           int bm, int bn, int tid) {
    int kw = chunk * 64;
    uint32_t base = sbu + stoff;
    // A: 128 rows x 8 segs of 16B
#pragma unroll
    for (int i = 0; i < 4; ++i) {
        int idx = tid + i * 256;
        int row = idx >> 3, q = idx & 7;
        cp16(base + swz((uint32_t)(row * 128 + q * 16)),
             &g_A[(size_t)(bm + row) * KTOT + kw + q * 8]);
    }
    // B: 64 k-rows x 16 segs of 16B (n-contiguous)
#pragma unroll
    for (int i = 0; i < 4; ++i) {
        int idx = tid + i * 256;
        int krow = idx >> 4, q = idx & 15;
        cp16(base + B_OFF + swz2((uint32_t)(krow * 256 + q * 16)),
             &g_cols[(size_t)(kw + krow) * NTOT + bn + q * 8]);
    }
}

__global__ __launch_bounds__(256, 2)
void gemm_mma_kernel(const float* __restrict__ bias,
                     const float* __restrict__ gamma,
                     const float* __restrict__ beta,
                     const float* __restrict__ rmean,
                     const float* __restrict__ rvar,
                     float* __restrict__ out) {
    extern __shared__ char smc[];
    uint32_t sbu = smem_u32(smc);
    int tid  = threadIdx.x;
    int lane = tid & 31;
    int wid  = tid >> 5;
    int bn = blockIdx.x * 128;
    int bm = blockIdx.y * 128;
    int warp_m = wid & 1;                 // 2 warps along M (64 rows each)
    int warp_n = wid >> 1;                // 4 warps along N (32 cols each)

    int mi   = lane >> 3;
    int mrow = lane & 7;
    int rbit = ((mi & 1) << 3) + mrow;
    int cbit = (mi >> 1) << 4;
    int klane = ((mi >> 1) << 3) + mrow;
    int nlane = (mi & 1) << 3;

    float acc[4][4][4];
#pragma unroll
    for (int a = 0; a < 4; ++a)
#pragma unroll
        for (int b2 = 0; b2 < 4; ++b2)
#pragma unroll
            for (int c2 = 0; c2 < 4; ++c2) acc[a][b2][c2] = 0.f;

    load_chunk(sbu, 0 * STAGEB, 0, bm, bn, tid); CP_COMMIT();
    load_chunk(sbu, 1 * STAGEB, 1, bm, bn, tid); CP_COMMIT();

    int arow0 = warp_m * 64;
    int brow0 = warp_n * 32;

    for (int i = 0; i < NCHUNK; ++i) {
        CP_WAIT1();
        __syncthreads();

        if (i + 2 < NCHUNK)
            load_chunk(sbu, (uint32_t)(((i + 2) % 3) * STAGEB), i + 2, bm, bn, tid);
        CP_COMMIT();

        uint32_t base = sbu + (i % 3) * STAGEB;
#pragma unroll
        for (int ks = 0; ks < 4; ++ks) {
            uint32_t bq[2][4], af[4][4];
#pragma unroll
            for (int ng = 0; ng < 2; ++ng)
                ldsm4t(bq[ng], base + B_OFF +
                       swz2((uint32_t)((ks * 16 + klane) * 256
                            + (brow0 + ng * 16 + nlane) * 2)));
#pragma unroll
            for (int mt = 0; mt < 4; ++mt)
                ldsm4(af[mt], base +
                      swz((uint32_t)((arow0 + mt * 16 + rbit) * 128 + ks * 32 + cbit)));

#pragma unroll
            for (int mt = 0; mt < 4; ++mt)
#pragma unroll
                for (int ng = 0; ng < 2; ++ng) {
                    mma16816(acc[mt][ng * 2 + 0], af[mt], bq[ng][0], bq[ng][2]);
                    mma16816(acc[mt][ng * 2 + 1], af[mt], bq[ng][1], bq[ng][3]);
                }
        }
    }

    // epilogue: BN + bias + ReLU, float2 stores
    int nbase = bn + warp_n * 32;
#pragma unroll
    for (int mt = 0; mt < 4; ++mt) {
        int o0 = bm + warp_m * 64 + mt * 16 + (lane >> 2);
        int o1 = o0 + 8;
        float inv0 = gamma[o0] * rsqrtf(rvar[o0] + 1e-5f);
        float sh0  = beta[o0] - rmean[o0] * inv0 + bias[o0] * inv0;
        float inv1 = gamma[o1] * rsqrtf(rvar[o1] + 1e-5f);
        float sh1  = beta[o1] - rmean[o1] * inv1 + bias[o1] * inv1;
#pragma unroll
        for (int nt = 0; nt < 4; ++nt) {
            int n = nbase + nt * 8 + ((lane & 3) << 1);
            int bimg = n >> 12;
            int hw   = n & 4095;
            float2 v0, v1;
            v0.x = fmaxf(fmaf(acc[mt][nt][0], inv0, sh0), 0.f);
            v0.y = fmaxf(fmaf(acc[mt][nt][1], inv0, sh0), 0.f);
            v1.x = fmaxf(fmaf(acc[mt][nt][2], inv1, sh1), 0.f);
            v1.y = fmaxf(fmaf(acc[mt][nt][3], inv1, sh1), 0.f);
            *(float2*)&out[(((size_t)(bimg * Oo + o0)) << 12) + hw] = v0;
            *(float2*)&out[(((size_t)(bimg * Oo + o1)) << 12) + hw] = v1;
        }
    }
}

// ===========================================================================
extern "C" void kernel_launch(void* const* d_in, const int* in_sizes, int n_in,
                              void* d_out, int out_size) {
    const float* x      = (const float*)d_in[0];
    const float* w_off  = (const float*)d_in[1];
    const float* b_off  = (const float*)d_in[2];
    const float* weight = (const float*)d_in[3];
    const float* bias   = (const float*)d_in[4];
    const float* gamma  = (const float*)d_in[5];
    const float* beta   = (const float*)d_in[6];
    const float* rmean  = (const float*)d_in[7];
    const float* rvar   = (const float*)d_in[8];
    float* out = (float*)d_out;

    cudaFuncSetAttribute(gemm_mma_kernel,
                         cudaFuncAttributeMaxDynamicSharedMemorySize, GSM);

    wprep_kernel<<<(Oo * KTOT + 255) / 256, 256>>>(weight);
    offset_conv_part<<<Bb * 16 * CSPLIT, 256>>>(x, w_off);
    build_cols_kernel<<<NTOT / 32, 288>>>(x, b_off);

    {
        dim3 grid(NTOT / 128, Oo / 128);
        gemm_mma_kernel<<<grid, 256, GSM>>>(bias, gamma, beta, rmean, rvar, out);
    }
}